// round 3
// baseline (speedup 1.0000x reference)
#include <cuda_runtime.h>

#define DIMV 64
#define GRAD_ELEMS 6400000   // N * DIM = 100000 * 64

// Aligned scratch for grad accumulation (d_out+1 is not 16B-aligned).
__device__ float g_grad[GRAD_ELEMS];

__device__ __forceinline__ void red_add_v4(float* addr, float a, float b, float c, float d) {
    asm volatile("red.global.add.v4.f32 [%0], {%1, %2, %3, %4};"
                 :: "l"(addr), "f"(a), "f"(b), "f"(c), "f"(d)
                 : "memory");
}

__global__ void zero_kernel(float* energy_out, int n_grad4) {
    int i = blockIdx.x * blockDim.x + threadIdx.x;
    if (i == 0) *energy_out = 0.0f;
    float4* g = reinterpret_cast<float4*>(g_grad);
    float4 z = make_float4(0.f, 0.f, 0.f, 0.f);
    for (int j = i; j < n_grad4; j += gridDim.x * blockDim.x)
        g[j] = z;
}

__global__ __launch_bounds__(256)
void edge_kernel(const float* __restrict__ x,
                 const int* __restrict__ u_idx,
                 const int* __restrict__ v_idx,
                 float* __restrict__ energy,
                 int E) {
    int gid  = blockIdx.x * blockDim.x + threadIdx.x;
    int edge = gid >> 3;       // 8 lanes per edge
    int sub  = gid & 7;        // lane-within-edge: owns dims [8*sub, 8*sub+8)

    float e_acc = 0.0f;

    if (edge < E) {
        int u = u_idx[edge];
        int v = v_idx[edge];

        const float4* pu = reinterpret_cast<const float4*>(x + (size_t)u * DIMV) + 2 * sub;
        const float4* pv = reinterpret_cast<const float4*>(x + (size_t)v * DIMV) + 2 * sub;
        float4 a0 = pu[0], a1 = pu[1];
        float4 b0 = pv[0], b1 = pv[1];

        // Minkowski signature: J[0] = -1 (dim 0 lives in sub==0's first slot)
        float sgn = (sub == 0) ? -1.0f : 1.0f;

        float partial = sgn * (a0.x * b0.x) + a0.y * b0.y + a0.z * b0.z + a0.w * b0.w
                      + a1.x * b1.x + a1.y * b1.y + a1.z * b1.z + a1.w * b1.w;

        // reduce across the 8-lane group (xor 1,2,4 stays within the group)
        partial += __shfl_xor_sync(0xffffffffu, partial, 1);
        partial += __shfl_xor_sync(0xffffffffu, partial, 2);
        partial += __shfl_xor_sync(0xffffffffu, partial, 4);

        float inner = fminf(partial, -1.0f - 1e-7f);
        float dist  = acoshf(-inner);

        if (dist < 0.1f) {
            float delta = 0.1f - dist;
            if (sub == 0) e_acc = 5.0f * delta * delta;   // 0.5*A/NUM_NEG = 5

            float denom  = sqrtf(inner * inner - 1.0f);
            float factor = -(10.0f * delta) / (denom + 1e-9f);   // A/NUM_NEG = 10

            float* du = g_grad + (size_t)u * DIMV + 8 * sub;
            float* dv = g_grad + (size_t)v * DIMV + 8 * sub;

            // grad[u] += factor * (xv * J);  grad[v] += factor * (xu * J)
            red_add_v4(du,     sgn * factor * b0.x, factor * b0.y, factor * b0.z, factor * b0.w);
            red_add_v4(du + 4, factor * b1.x,       factor * b1.y, factor * b1.z, factor * b1.w);
            red_add_v4(dv,     sgn * factor * a0.x, factor * a0.y, factor * a0.z, factor * a0.w);
            red_add_v4(dv + 4, factor * a1.x,       factor * a1.y, factor * a1.z, factor * a1.w);
        }
    }

    // block-level energy reduction -> one atomic per block
    e_acc += __shfl_xor_sync(0xffffffffu, e_acc, 16);
    e_acc += __shfl_xor_sync(0xffffffffu, e_acc, 8);
    e_acc += __shfl_xor_sync(0xffffffffu, e_acc, 4);
    e_acc += __shfl_xor_sync(0xffffffffu, e_acc, 2);
    e_acc += __shfl_xor_sync(0xffffffffu, e_acc, 1);

    __shared__ float smem[8];
    int warp = threadIdx.x >> 5;
    int lane = threadIdx.x & 31;
    if (lane == 0) smem[warp] = e_acc;
    __syncthreads();
    if (warp == 0) {
        float s = (lane < 8) ? smem[lane] : 0.0f;
        s += __shfl_xor_sync(0xffffffffu, s, 4);
        s += __shfl_xor_sync(0xffffffffu, s, 2);
        s += __shfl_xor_sync(0xffffffffu, s, 1);
        if (lane == 0 && s != 0.0f) atomicAdd(energy, s);
    }
}

// Copy aligned scratch -> unaligned output region (d_out + 1)
__global__ void copy_kernel(float* __restrict__ out_grad, int n_grad4) {
    int i = blockIdx.x * blockDim.x + threadIdx.x;
    const float4* g = reinterpret_cast<const float4*>(g_grad);
    for (int j = i; j < n_grad4; j += gridDim.x * blockDim.x) {
        float4 val = g[j];
        out_grad[4 * j + 0] = val.x;
        out_grad[4 * j + 1] = val.y;
        out_grad[4 * j + 2] = val.z;
        out_grad[4 * j + 3] = val.w;
    }
}

extern "C" void kernel_launch(void* const* d_in, const int* in_sizes, int n_in,
                              void* d_out, int out_size) {
    const float* x     = (const float*)d_in[0];
    const int*   u_idx = (const int*)d_in[1];
    const int*   v_idx = (const int*)d_in[2];
    float*       out   = (float*)d_out;

    int E  = in_sizes[1];          // number of edges (N * NUM_NEG)
    int n4 = in_sizes[0] / 4;      // grad float4 count

    zero_kernel<<<2048, 256>>>(out, n4);

    long long total_lanes = (long long)E * 8;
    int blocks = (int)((total_lanes + 255) / 256);
    edge_kernel<<<blocks, 256>>>(x, u_idx, v_idx, out, E);

    copy_kernel<<<2048, 256>>>(out + 1, n4);
}

// round 4
// speedup vs baseline: 1.0563x; 1.0563x over previous
#include <cuda_runtime.h>

#define DIMV 64
#define GRAD_ELEMS 6400000   // N * DIM = 100000 * 64

// Aligned scratch for grad accumulation (d_out+1 is not 16B-aligned).
// Zero-initialized at module load; every kernel_launch call restores it to
// zero (copy_kernel writes zeros back after reading), so it is always zero
// on entry. Same for g_energy.
__device__ float g_grad[GRAD_ELEMS];
__device__ float g_energy;

__device__ __forceinline__ void red_add_v4(float* addr, float a, float b, float c, float d) {
    asm volatile("red.global.add.v4.f32 [%0], {%1, %2, %3, %4};"
                 :: "l"(addr), "f"(a), "f"(b), "f"(c), "f"(d)
                 : "memory");
}

__device__ __forceinline__ void red_add_f32(float* addr, float a) {
    asm volatile("red.global.add.f32 [%0], %1;"
                 :: "l"(addr), "f"(a)
                 : "memory");
}

__global__ __launch_bounds__(512)
void edge_kernel(const float* __restrict__ x,
                 const int* __restrict__ u_idx,
                 const int* __restrict__ v_idx,
                 int E) {
    int gid  = blockIdx.x * blockDim.x + threadIdx.x;
    int edge = gid >> 3;       // 8 lanes per edge
    int sub  = gid & 7;        // lane-within-edge: owns dims [8*sub, 8*sub+8)

    float e_acc = 0.0f;

    if (edge < E) {
        int u = u_idx[edge];
        int v = v_idx[edge];

        const float4* pu = reinterpret_cast<const float4*>(x + (size_t)u * DIMV) + 2 * sub;
        const float4* pv = reinterpret_cast<const float4*>(x + (size_t)v * DIMV) + 2 * sub;
        float4 a0 = pu[0], a1 = pu[1];
        float4 b0 = pv[0], b1 = pv[1];

        // Minkowski signature: J[0] = -1 (dim 0 lives in sub==0's first slot)
        float sgn = (sub == 0) ? -1.0f : 1.0f;

        float partial = sgn * (a0.x * b0.x) + a0.y * b0.y + a0.z * b0.z + a0.w * b0.w
                      + a1.x * b1.x + a1.y * b1.y + a1.z * b1.z + a1.w * b1.w;

        // reduce across the 8-lane group (xor 1,2,4 stays within the group)
        partial += __shfl_xor_sync(0xffffffffu, partial, 1);
        partial += __shfl_xor_sync(0xffffffffu, partial, 2);
        partial += __shfl_xor_sync(0xffffffffu, partial, 4);

        float inner = fminf(partial, -1.0f - 1e-7f);
        float dist  = acoshf(-inner);

        if (dist < 0.1f) {
            float delta = 0.1f - dist;
            if (sub == 0) e_acc = 5.0f * delta * delta;   // 0.5*A/NUM_NEG = 5

            float denom  = sqrtf(inner * inner - 1.0f);
            float factor = -(10.0f * delta) / (denom + 1e-9f);   // A/NUM_NEG = 10

            float* du = g_grad + (size_t)u * DIMV + 8 * sub;
            float* dv = g_grad + (size_t)v * DIMV + 8 * sub;

            // grad[u] += factor * (xv * J);  grad[v] += factor * (xu * J)
            red_add_v4(du,     sgn * factor * b0.x, factor * b0.y, factor * b0.z, factor * b0.w);
            red_add_v4(du + 4, factor * b1.x,       factor * b1.y, factor * b1.z, factor * b1.w);
            red_add_v4(dv,     sgn * factor * a0.x, factor * a0.y, factor * a0.z, factor * a0.w);
            red_add_v4(dv + 4, factor * a1.x,       factor * a1.y, factor * a1.z, factor * a1.w);
        }
    }

    // block-level energy reduction -> one RED (no return) per block
    e_acc += __shfl_xor_sync(0xffffffffu, e_acc, 16);
    e_acc += __shfl_xor_sync(0xffffffffu, e_acc, 8);
    e_acc += __shfl_xor_sync(0xffffffffu, e_acc, 4);
    e_acc += __shfl_xor_sync(0xffffffffu, e_acc, 2);
    e_acc += __shfl_xor_sync(0xffffffffu, e_acc, 1);

    __shared__ float smem[16];
    int warp = threadIdx.x >> 5;
    int lane = threadIdx.x & 31;
    if (lane == 0) smem[warp] = e_acc;
    __syncthreads();
    if (warp == 0) {
        float s = (lane < 16) ? smem[lane] : 0.0f;
        s += __shfl_xor_sync(0xffffffffu, s, 8);
        s += __shfl_xor_sync(0xffffffffu, s, 4);
        s += __shfl_xor_sync(0xffffffffu, s, 2);
        s += __shfl_xor_sync(0xffffffffu, s, 1);
        if (lane == 0 && s != 0.0f) red_add_f32(&g_energy, s);
    }
}

// Copy aligned scratch -> unaligned output region (d_out + 1), AND restore the
// scratch (g_grad, g_energy) to zero for the next kernel_launch call.
// Exact-fit grid: one float4 per thread.
__global__ __launch_bounds__(512)
void copy_restore_kernel(float* __restrict__ out, int n_grad4) {
    int j = blockIdx.x * blockDim.x + threadIdx.x;
    if (j < n_grad4) {
        float4* g = reinterpret_cast<float4*>(g_grad);
        float4 val = g[j];
        float* out_grad = out + 1;
        out_grad[4 * j + 0] = val.x;
        out_grad[4 * j + 1] = val.y;
        out_grad[4 * j + 2] = val.z;
        out_grad[4 * j + 3] = val.w;
        g[j] = make_float4(0.f, 0.f, 0.f, 0.f);
    }
    if (j == 0) {
        out[0] = g_energy;
        g_energy = 0.0f;
    }
}

extern "C" void kernel_launch(void* const* d_in, const int* in_sizes, int n_in,
                              void* d_out, int out_size) {
    const float* x     = (const float*)d_in[0];
    const int*   u_idx = (const int*)d_in[1];
    const int*   v_idx = (const int*)d_in[2];
    float*       out   = (float*)d_out;

    int E  = in_sizes[1];          // number of edges (N * NUM_NEG)
    int n4 = in_sizes[0] / 4;      // grad float4 count

    long long total_lanes = (long long)E * 8;
    int eblocks = (int)((total_lanes + 511) / 512);
    edge_kernel<<<eblocks, 512>>>(x, u_idx, v_idx, E);

    int cblocks = (n4 + 511) / 512;
    copy_restore_kernel<<<cblocks, 512>>>(out, n4);
}

// round 6
// speedup vs baseline: 1.1023x; 1.0435x over previous
#include <cuda_runtime.h>

#define DIMV 64
#define GRAD_ELEMS 6400000   // N * DIM = 100000 * 64
#define MAX_NODES  100000
#define CAP        64        // per-node edge slot capacity (Poisson(10) tail ~0)

// All __device__ globals are zero at module load; copy_restore_kernel returns
// them to zero at the end of every kernel_launch call, so each call starts
// from a zeroed state (graph replays are stream-ordered).
__device__ float g_grad[GRAD_ELEMS];
__device__ float g_energy;
__device__ int   g_cnt[MAX_NODES];
__device__ int   g_slots[MAX_NODES * CAP];

__device__ __forceinline__ void red_add_v4(float* addr, float a, float b, float c, float d) {
    asm volatile("red.global.add.v4.f32 [%0], {%1, %2, %3, %4};"
                 :: "l"(addr), "f"(a), "f"(b), "f"(c), "f"(d)
                 : "memory");
}
__device__ __forceinline__ void red_add_f32(float* addr, float a) {
    asm volatile("red.global.add.f32 [%0], %1;"
                 :: "l"(addr), "f"(a) : "memory");
}

// ---------------------------------------------------------------------------
// Phase 1: bin edges by u into fixed-capacity slots. Overflow edges (virtually
// impossible for Poisson(10) vs CAP=64, but handled for correctness) are
// processed inline, edge-parallel style.
// ---------------------------------------------------------------------------
__global__ __launch_bounds__(512)
void build_kernel(const float* __restrict__ x,
                  const int* __restrict__ u_idx,
                  const int* __restrict__ v_idx,
                  int E) {
    int e = blockIdx.x * blockDim.x + threadIdx.x;
    if (e >= E) return;
    int u = u_idx[e];
    int v = v_idx[e];
    int pos = atomicAdd(&g_cnt[u], 1);
    if (pos < CAP) {
        g_slots[u * CAP + pos] = v;
        return;
    }
    // --- overflow fallback: full per-edge computation, scalar ---
    const float* xu = x + (size_t)u * DIMV;
    const float* xv = x + (size_t)v * DIMV;
    float dot = -xu[0] * xv[0];
    for (int k = 1; k < DIMV; k++) dot += xu[k] * xv[k];
    float inner = fminf(dot, -1.0f - 1e-7f);
    float dist  = acoshf(-inner);
    if (dist < 0.1f) {
        float delta  = 0.1f - dist;
        float denom  = sqrtf(inner * inner - 1.0f);
        float factor = -(10.0f * delta) / (denom + 1e-9f);
        red_add_f32(&g_energy, 5.0f * delta * delta);
        float* gu = g_grad + (size_t)u * DIMV;
        float* gv = g_grad + (size_t)v * DIMV;
        atomicAdd(gu + 0, -factor * xv[0]);
        atomicAdd(gv + 0, -factor * xu[0]);
        for (int k = 1; k < DIMV; k++) {
            atomicAdd(gu + k, factor * xv[k]);
            atomicAdd(gv + k, factor * xu[k]);
        }
    }
}

// ---------------------------------------------------------------------------
// Phase 2: node-centric. 8 lanes per node u. xu loaded once; u-grad kept in
// registers across the run; one red.v4 pair per lane per node at the end.
// NOTE: in-loop shuffles use the 8-lane GROUP mask — trip count (cnt) differs
// per group within a warp, so a full-mask sync shuffle would deadlock.
// ---------------------------------------------------------------------------
__global__ __launch_bounds__(512)
void node_kernel(const float* __restrict__ x, int N) {
    int gid  = blockIdx.x * blockDim.x + threadIdx.x;
    int u    = gid >> 3;
    int sub  = gid & 7;
    int lane = threadIdx.x & 31;
    unsigned gmask = 0xFFu << (lane & ~7);   // this 8-lane group's lanes

    float e_acc = 0.0f;

    if (u < N) {
        const float4* pu = reinterpret_cast<const float4*>(x + (size_t)u * DIMV) + 2 * sub;
        float4 a0 = pu[0], a1 = pu[1];
        float sgn = (sub == 0) ? -1.0f : 1.0f;

        int cnt = g_cnt[u];
        if (cnt > CAP) cnt = CAP;
        const int* slots = g_slots + u * CAP;

        float4 ua0 = make_float4(0.f, 0.f, 0.f, 0.f);
        float4 ua1 = make_float4(0.f, 0.f, 0.f, 0.f);
        bool any_active = false;

        for (int i = 0; i < cnt; i++) {
            int v = slots[i];
            const float4* pv = reinterpret_cast<const float4*>(x + (size_t)v * DIMV) + 2 * sub;
            float4 b0 = pv[0], b1 = pv[1];

            float partial = sgn * (a0.x * b0.x) + a0.y * b0.y + a0.z * b0.z + a0.w * b0.w
                          + a1.x * b1.x + a1.y * b1.y + a1.z * b1.z + a1.w * b1.w;
            partial += __shfl_xor_sync(gmask, partial, 1);
            partial += __shfl_xor_sync(gmask, partial, 2);
            partial += __shfl_xor_sync(gmask, partial, 4);

            float inner = fminf(partial, -1.0f - 1e-7f);
            float dist  = acoshf(-inner);

            if (dist < 0.1f) {
                any_active = true;
                float delta  = 0.1f - dist;
                if (sub == 0) e_acc += 5.0f * delta * delta;

                float denom  = sqrtf(inner * inner - 1.0f);
                float factor = -(10.0f * delta) / (denom + 1e-9f);

                // accumulate grad[u] += factor * (xv ∘ J) in registers
                ua0.x += sgn * factor * b0.x;
                ua0.y += factor * b0.y;  ua0.z += factor * b0.z;  ua0.w += factor * b0.w;
                ua1.x += factor * b1.x;  ua1.y += factor * b1.y;
                ua1.z += factor * b1.z;  ua1.w += factor * b1.w;

                // grad[v] += factor * (xu ∘ J): scatter now
                float* dv = g_grad + (size_t)v * DIMV + 8 * sub;
                red_add_v4(dv,     sgn * factor * a0.x, factor * a0.y, factor * a0.z, factor * a0.w);
                red_add_v4(dv + 4, factor * a1.x,       factor * a1.y, factor * a1.z, factor * a1.w);
            }
        }

        if (any_active) {
            float* du = g_grad + (size_t)u * DIMV + 8 * sub;
            red_add_v4(du,     ua0.x, ua0.y, ua0.z, ua0.w);
            red_add_v4(du + 4, ua1.x, ua1.y, ua1.z, ua1.w);
        }
    }

    // block-level energy reduction (all lanes reconverged here) -> one RED per block
    e_acc += __shfl_xor_sync(0xffffffffu, e_acc, 16);
    e_acc += __shfl_xor_sync(0xffffffffu, e_acc, 8);
    e_acc += __shfl_xor_sync(0xffffffffu, e_acc, 4);
    e_acc += __shfl_xor_sync(0xffffffffu, e_acc, 2);
    e_acc += __shfl_xor_sync(0xffffffffu, e_acc, 1);

    __shared__ float smem[16];
    int warp = threadIdx.x >> 5;
    if (lane == 0) smem[warp] = e_acc;
    __syncthreads();
    if (warp == 0) {
        float s = (lane < 16) ? smem[lane] : 0.0f;
        s += __shfl_xor_sync(0xffffffffu, s, 8);
        s += __shfl_xor_sync(0xffffffffu, s, 4);
        s += __shfl_xor_sync(0xffffffffu, s, 2);
        s += __shfl_xor_sync(0xffffffffu, s, 1);
        if (lane == 0 && s != 0.0f) red_add_f32(&g_energy, s);
    }
}

// ---------------------------------------------------------------------------
// Phase 3: copy grad -> d_out (unaligned by 1 float), write energy, and
// restore all scratch state (g_grad, g_energy, g_cnt) to zero.
// ---------------------------------------------------------------------------
__global__ __launch_bounds__(512)
void copy_restore_kernel(float* __restrict__ out, int n_grad4) {
    int j = blockIdx.x * blockDim.x + threadIdx.x;
    if (j < n_grad4) {
        float4* g = reinterpret_cast<float4*>(g_grad);
        float4 val = g[j];
        float* out_grad = out + 1;
        out_grad[4 * j + 0] = val.x;
        out_grad[4 * j + 1] = val.y;
        out_grad[4 * j + 2] = val.z;
        out_grad[4 * j + 3] = val.w;
        g[j] = make_float4(0.f, 0.f, 0.f, 0.f);
    }
    if (j < MAX_NODES) g_cnt[j] = 0;
    if (j == 0) {
        out[0] = g_energy;
        g_energy = 0.0f;
    }
}

extern "C" void kernel_launch(void* const* d_in, const int* in_sizes, int n_in,
                              void* d_out, int out_size) {
    const float* x     = (const float*)d_in[0];
    const int*   u_idx = (const int*)d_in[1];
    const int*   v_idx = (const int*)d_in[2];
    float*       out   = (float*)d_out;

    int E  = in_sizes[1];          // number of edges (N * NUM_NEG)
    int n4 = in_sizes[0] / 4;      // grad float4 count
    int N  = in_sizes[0] / DIMV;   // number of nodes

    build_kernel<<<(E + 511) / 512, 512>>>(x, u_idx, v_idx, E);

    long long lanes = (long long)N * 8;
    node_kernel<<<(int)((lanes + 511) / 512), 512>>>(x, N);

    copy_restore_kernel<<<(n4 + 511) / 512, 512>>>(out, n4);
}